// round 12
// baseline (speedup 1.0000x reference)
#include <cuda_runtime.h>

#define Bb 8
#define Nn 4096
#define NC 13
#define BN (Bb*Nn)        // 32768 points per set
#define TPB 128
#define QPT 8
#define QPB (TPB*QPT)     // 1024 queries (rec rows) per block
#define NQB (Nn/QPB)      // 4 query blocks per batch
#define CSN 16            // candidate slices per batch
#define SC (Nn/CSN)       // 256 candidates (pt cols) per block
#define NBLK (Bb*NQB*CSN) // 512
#define NRG (Bb*NQB)      // 32 row groups, CSN=16 arrivals
#define NCG (Bb*CSN)      // 128 col groups, NQB=4 arrivals
#define ENC 0x7F800000    // k = ENC - float_bits(d); 0 == +inf; min d == max k
#define INFF 3.4e38f

typedef unsigned long long u64;

__device__ int          g_rmin[BN];      // encoded row mins (rec->pt); 0==+inf; leader-reset
__device__ int          g_cmin[BN];      // encoded col mins (pt->rec)
__device__ float        g_rowpart[NRG];
__device__ float        g_colpart[NCG];
__device__ float        g_fpart[NBLK];   // per-block seg sums
__device__ unsigned int g_rowtk[NRG];    // zero-init; self-reset
__device__ unsigned int g_coltk[NCG];
__device__ unsigned int g_ticket;        // counts row+col leaders = 160

// ---- f32x2 helpers ----------------------------------------------------------
__device__ __forceinline__ u64 pk(float lo, float hi) {
    u64 r; asm("mov.b64 %0, {%1, %2};" : "=l"(r) : "f"(lo), "f"(hi)); return r;
}
__device__ __forceinline__ u64 fma2(u64 a, u64 b, u64 c) {
    u64 d; asm("fma.rn.f32x2 %0, %1, %2, %3;" : "=l"(d) : "l"(a), "l"(b), "l"(c)); return d;
}
__device__ __forceinline__ u64 add2(u64 a, u64 b) {
    u64 d; asm("add.rn.f32x2 %0, %1, %2;" : "=l"(d) : "l"(a), "l"(b)); return d;
}
__device__ __forceinline__ void upk(u64 v, float& lo, float& hi) {
    asm("mov.b64 {%0, %1}, %2;" : "=f"(lo), "=f"(hi) : "l"(v));
}

// ---- single fused symmetric kernel -------------------------------------------
// grid (CSN, NQB, Bb) = (16,4,8): x = cand slice, y = qblk, z = batch
// Layout: 2 queries packed per f32x2 lane; candidate duplicated -> 1 REDUX/candidate
__global__ void __launch_bounds__(TPB, 5) fused_kernel(const float* __restrict__ rec,
                                                       const float* __restrict__ pt,
                                                       const float* __restrict__ prob,
                                                       const void* __restrict__ lab,
                                                       float* __restrict__ out) {
    __shared__ ulonglong2 scd[2*SC];    // 8KB: cand j -> [2j]={xx,yy} [2j+1]={zz,nn} (dup)
    __shared__ unsigned   scolp[4*SC];  // 4KB: per-warp col-min bits
    __shared__ float      sred[TPB];
    __shared__ int        s_is64, s_rowfin, s_colfin, s_last;

    const int cs   = blockIdx.x;
    const int qblk = blockIdx.y;
    const int b    = blockIdx.z;
    const int t    = threadIdx.x;
    const int w    = t >> 5;
    const int bl   = (b * NQB + qblk) * CSN + cs;  // [0,512)
    const int rowg = b * NQB + qblk;               // [0,32)
    const int colg = b * CSN + cs;                 // [0,128)

    if (t == 0) { s_is64 = 1; s_rowfin = 0; s_colfin = 0; s_last = 0; }
    __syncthreads();
    // labels < 13; if int64 every odd 32-bit word is 0 (probe 128 labels)
    if (((const int*)lab)[2 * t + 1] != 0) s_is64 = 0;

    // queries = rec rows: chain c packs queries (t + 2c*TPB, t + (2c+1)*TPB)
    const int qbase = b * Nn + qblk * QPB;
    u64 qx2[QPT/2], qy2[QPT/2], qz2[QPT/2], qn2[QPT/2];
    #pragma unroll
    for (int c = 0; c < QPT/2; c++) {
        const float* pa = rec + (size_t)(qbase + t + (2*c)   * TPB) * 3;
        const float* pb = rec + (size_t)(qbase + t + (2*c+1) * TPB) * 3;
        float xa = pa[0], ya = pa[1], za = pa[2];
        float xb = pb[0], yb = pb[1], zb = pb[2];
        float na = fmaf(xa, xa, fmaf(ya, ya, za * za));
        float nb = fmaf(xb, xb, fmaf(yb, yb, zb * zb));
        qx2[c] = pk(-2.f * xa, -2.f * xb);
        qy2[c] = pk(-2.f * ya, -2.f * yb);
        qz2[c] = pk(-2.f * za, -2.f * zb);
        qn2[c] = pk(na, nb);
    }

    // candidates = pt cols: stage duplicated (2 per thread)
    {
        const int cbase = b * Nn + cs * SC;
        #pragma unroll
        for (int i = 0; i < SC / TPB; i++) {
            int j = t + i * TPB;
            const float* c = pt + (size_t)(cbase + j) * 3;
            float x = c[0], y = c[1], z = c[2];
            float n = fmaf(x, x, fmaf(y, y, z * z));
            scd[2 * j]     = make_ulonglong2(pk(x, x), pk(y, y));
            scd[2 * j + 1] = make_ulonglong2(pk(z, z), pk(n, n));
        }
    }
    __syncthreads();

    float m0 = INFF, m1 = INFF, m2 = INFF, m3 = INFF;
    float m4 = INFF, m5 = INFF, m6 = INFF, m7 = INFF;

    #pragma unroll 4
    for (int j = 0; j < SC; j++) {
        ulonglong2 p0 = scd[2 * j];      // {cx,cx},{cy,cy}
        ulonglong2 p1 = scd[2 * j + 1];  // {cz,cz},{cn,cn}
        u64 t0 = fma2(qx2[0], p0.x, fma2(qy2[0], p0.y, fma2(qz2[0], p1.x, add2(p1.y, qn2[0]))));
        u64 t1 = fma2(qx2[1], p0.x, fma2(qy2[1], p0.y, fma2(qz2[1], p1.x, add2(p1.y, qn2[1]))));
        u64 t2 = fma2(qx2[2], p0.x, fma2(qy2[2], p0.y, fma2(qz2[2], p1.x, add2(p1.y, qn2[2]))));
        u64 t3 = fma2(qx2[3], p0.x, fma2(qy2[3], p0.y, fma2(qz2[3], p1.x, add2(p1.y, qn2[3]))));
        float l0, h0, l1, h1, l2, h2, l3, h3;
        upk(t0, l0, h0); upk(t1, l1, h1); upk(t2, l2, h2); upk(t3, l3, h3);
        // row mins (8 queries)
        m0 = fminf(m0, l0); m1 = fminf(m1, h0);
        m2 = fminf(m2, l1); m3 = fminf(m3, h1);
        m4 = fminf(m4, l2); m5 = fminf(m5, h2);
        m6 = fminf(m6, l3); m7 = fminf(m7, h3);
        // col min: reduce 8 queries in-thread, ONE REDUX across lanes
        float cv = fminf(fminf(fminf(l0, h0), fminf(l1, h1)),
                         fminf(fminf(l2, h2), fminf(l3, h3)));
        unsigned ra = __reduce_min_sync(0xffffffffu, __float_as_uint(cv));
        if ((t & 31) == 0) scolp[w * SC + j] = ra;
    }

    // row mins -> global encoded
    {
        int* gm = g_rmin + b * Nn + qblk * QPB + t;
        atomicMax(gm,           ENC - __float_as_int(m0));
        atomicMax(gm + TPB,     ENC - __float_as_int(m1));
        atomicMax(gm + 2 * TPB, ENC - __float_as_int(m2));
        atomicMax(gm + 3 * TPB, ENC - __float_as_int(m3));
        atomicMax(gm + 4 * TPB, ENC - __float_as_int(m4));
        atomicMax(gm + 5 * TPB, ENC - __float_as_int(m5));
        atomicMax(gm + 6 * TPB, ENC - __float_as_int(m6));
        atomicMax(gm + 7 * TPB, ENC - __float_as_int(m7));
    }
    __syncthreads();

    // col mins: combine 4 warps; thread handles candidates t and t+TPB
    #pragma unroll
    for (int i = 0; i < SC / TPB; i++) {
        int j = t + i * TPB;
        unsigned a = min(min(scolp[j], scolp[SC + j]),
                         min(scolp[2 * SC + j], scolp[3 * SC + j]));
        atomicMax(g_cmin + b * Nn + cs * SC + j, ENC - (int)a);
    }

    // seg NLL: 64 points per block (warp 0, 2 each)
    if (t < 32) {
        int idx = bl * 64 + t;
        int lb0, lb1;
        if (s_is64) {
            lb0 = (int)((const long long*)lab)[idx];
            lb1 = (int)((const long long*)lab)[idx + 32];
        } else {
            lb0 = ((const int*)lab)[idx];
            lb1 = ((const int*)lab)[idx + 32];
        }
        float v = prob[idx * NC + lb0] + prob[(idx + 32) * NC + lb1];
        #pragma unroll
        for (int off = 16; off > 0; off >>= 1)
            v += __shfl_xor_sync(0xffffffffu, v, off);
        if (t == 0) g_fpart[bl] = v;
    }

    // publish: one gpu fence per block (t0), then group tickets
    __syncthreads();
    if (t == 0) {
        __threadfence();
        if (atomicAdd(&g_rowtk[rowg], 1u) == (unsigned)(CSN - 1)) s_rowfin = 1;
        if (atomicAdd(&g_coltk[colg], 1u) == (unsigned)(NQB - 1)) s_colfin = 1;
    }
    __syncthreads();

    if (s_rowfin) {   // row leader: sum 1024 query mins; reset
        int4* base = (int4*)(g_rmin + b * Nn + qblk * QPB);
        float acc = 0.f;
        #pragma unroll
        for (int i = 0; i < QPB / 4 / TPB; i++) {
            int4 v = __ldcg(base + t + i * TPB);
            acc += (__int_as_float(ENC - v.x) + __int_as_float(ENC - v.y)) +
                   (__int_as_float(ENC - v.z) + __int_as_float(ENC - v.w));
            __stcg(base + t + i * TPB, make_int4(0, 0, 0, 0));
        }
        sred[t] = acc;
        __syncthreads();
        #pragma unroll
        for (int s = 64; s > 0; s >>= 1) {
            if (t < s) sred[t] += sred[t + s];
            __syncthreads();
        }
        if (t == 0) {
            g_rowpart[rowg] = sred[0];
            g_rowtk[rowg] = 0u;
            __threadfence();
            if (atomicAdd(&g_ticket, 1u) == (unsigned)(NRG + NCG - 1)) s_last = 1;
        }
        __syncthreads();
    }
    if (s_colfin) {   // col leader: sum 256 candidate mins; reset
        float acc = 0.f;
        if (t < SC / 4) {
            int4* base = (int4*)(g_cmin + b * Nn + cs * SC);
            int4 v = __ldcg(base + t);
            acc = (__int_as_float(ENC - v.x) + __int_as_float(ENC - v.y)) +
                  (__int_as_float(ENC - v.z) + __int_as_float(ENC - v.w));
            __stcg(base + t, make_int4(0, 0, 0, 0));
        }
        sred[t] = acc;
        __syncthreads();
        #pragma unroll
        for (int s = 64; s > 0; s >>= 1) {
            if (t < s) sred[t] += sred[t + s];
            __syncthreads();
        }
        if (t == 0) {
            g_colpart[colg] = sred[0];
            g_coltk[colg] = 0u;
            __threadfence();
            if (atomicAdd(&g_ticket, 1u) == (unsigned)(NRG + NCG - 1)) s_last = 1;
        }
        __syncthreads();
    }

    __syncthreads();
    if (s_last) {     // final deterministic combine (one block, L2 reads)
        float v = __ldcg(&g_colpart[t]);              // 128 col-group sums
        if (t < NRG) v += __ldcg(&g_rowpart[t]);      // 32 row-group sums
        float sp = 0.f;
        #pragma unroll
        for (int k = 0; k < NBLK / TPB; k++)
            sp += __ldcg(&g_fpart[t + k * TPB]);      // 512 seg partials
        sred[t] = v - sp;
        __syncthreads();
        #pragma unroll
        for (int s = 64; s > 0; s >>= 1) {
            if (t < s) sred[t] += sred[t + s];
            __syncthreads();
        }
        if (t == 0) {
            out[0] = sred[0] * (1.0f / (float)BN);
            g_ticket = 0u;   // reset for next graph replay
        }
    }
}

extern "C" void kernel_launch(void* const* d_in, const int* in_sizes, int n_in,
                              void* d_out, int out_size) {
    const float* seg_prob  = (const float*)d_in[0];
    const void*  seg_label = (const void*)d_in[1];
    const float* point_rec = (const float*)d_in[2];
    const float* point     = (const float*)d_in[3];

    fused_kernel<<<dim3(CSN, NQB, Bb), TPB>>>(point_rec, point, seg_prob, seg_label,
                                              (float*)d_out);
}

// round 13
// speedup vs baseline: 1.9303x; 1.9303x over previous
#include <cuda_runtime.h>

#define Bb 8
#define Nn 4096
#define NC 13
#define BN (Bb*Nn)        // 32768 points per set
#define TPB 128
#define QPT 4
#define QPB (TPB*QPT)     // 512 queries (rec rows) per block
#define CSN 16            // candidate slices per batch
#define SC (Nn/CSN)       // 256 candidates (pt cols) per block
#define SP (SC/2)         // 128 candidate pairs
#define NBLK (Bb*8*CSN)   // 1024
#define NRG (Bb*8)        // 64 row groups (b,qblk), 16 arrivals
#define NCG (Bb*CSN)      // 128 col groups (b,cs), 8 arrivals
#define DUMP 160          // per-warp garbage-store region (u64 slots)
#define ENC 0x7F800000    // k = ENC - float_bits(d); 0 == +inf; min d == max k
#define INFF 3.4e38f

typedef unsigned long long u64;

__device__ int          g_rmin[BN];      // encoded row mins (rec->pt); 0==+inf; leader-reset
__device__ int          g_cmin[BN];      // encoded col mins (pt->rec)
__device__ float        g_rowpart[NRG];
__device__ float        g_colpart[NCG];
__device__ float        g_fpart[NBLK];   // per-block seg sums
__device__ unsigned int g_rowtk[NRG];    // zero-init; self-reset
__device__ unsigned int g_coltk[NCG];
__device__ unsigned int g_ticket;        // counts row+col leaders = 192

// ---- f32x2 helpers ----------------------------------------------------------
__device__ __forceinline__ u64 pk(float lo, float hi) {
    u64 r; asm("mov.b64 %0, {%1, %2};" : "=l"(r) : "f"(lo), "f"(hi)); return r;
}
__device__ __forceinline__ u64 fma2(u64 a, u64 b, u64 c) {
    u64 d; asm("fma.rn.f32x2 %0, %1, %2, %3;" : "=l"(d) : "l"(a), "l"(b), "l"(c)); return d;
}
__device__ __forceinline__ u64 add2(u64 a, u64 b) {
    u64 d; asm("add.rn.f32x2 %0, %1, %2;" : "=l"(d) : "l"(a), "l"(b)); return d;
}
__device__ __forceinline__ void upk(u64 v, float& lo, float& hi) {
    asm("mov.b64 {%0, %1}, %2;" : "=f"(lo), "=f"(hi) : "l"(v));
}

// ---- single fused symmetric kernel -------------------------------------------
// grid (CSN, 8, Bb) = (16,8,8): x = cand slice, y = qblk, z = batch
__global__ void __launch_bounds__(TPB, 7) fused_kernel(const float* __restrict__ rec,
                                                       const float* __restrict__ pt,
                                                       const float* __restrict__ prob,
                                                       const void* __restrict__ lab,
                                                       float* __restrict__ out) {
    __shared__ ulonglong2 scd[SC];        // 4KB: SP pairs x 2 entries
    __shared__ u64        scolp[4*SP];    // 4KB: per-warp packed col-min pairs
    __shared__ u64        sdump[4*DUMP];  // 5KB: garbage sink for lanes 1..31 (branch-free STS)
    __shared__ float      sred[TPB];
    __shared__ int        s_is64, s_rowfin, s_colfin, s_last;

    const int cs   = blockIdx.x;
    const int qblk = blockIdx.y;
    const int b    = blockIdx.z;
    const int t    = threadIdx.x;
    const int w    = t >> 5;
    const int lane = t & 31;
    const int bl   = (b * 8 + qblk) * CSN + cs;   // [0,1024)
    const int rowg = b * 8 + qblk;                // [0,64)
    const int colg = b * CSN + cs;                // [0,128)

    if (t == 0) { s_is64 = 1; s_rowfin = 0; s_colfin = 0; s_last = 0; }
    __syncthreads();
    // labels < 13; if int64 every odd 32-bit word is 0 (probe 128 labels)
    if (((const int*)lab)[2 * t + 1] != 0) s_is64 = 0;

    // queries = rec rows: pack dup(-2x/-2y/-2z) and dup(qn)
    const int qbase = b * Nn + qblk * QPB;
    u64 qx2[QPT], qy2[QPT], qz2[QPT], qn2[QPT];
    #pragma unroll
    for (int k = 0; k < QPT; k++) {
        const float* p = rec + (size_t)(qbase + t + k * TPB) * 3;
        float x = p[0], y = p[1], z = p[2];
        float n = fmaf(x, x, fmaf(y, y, z * z));
        qx2[k] = pk(-2.f * x, -2.f * x);
        qy2[k] = pk(-2.f * y, -2.f * y);
        qz2[k] = pk(-2.f * z, -2.f * z);
        qn2[k] = pk(n, n);
    }

    // candidates = pt cols: stage + pack one pair per thread
    {
        const int cbase = b * Nn + cs * SC;
        const float* c = pt + (size_t)(cbase + 2 * t) * 3;
        float x0 = c[0], y0 = c[1], z0 = c[2];
        float x1 = c[3], y1 = c[4], z1 = c[5];
        float n0 = fmaf(x0, x0, fmaf(y0, y0, z0 * z0));
        float n1 = fmaf(x1, x1, fmaf(y1, y1, z1 * z1));
        scd[2 * t]     = make_ulonglong2(pk(x0, x1), pk(y0, y1));
        scd[2 * t + 1] = make_ulonglong2(pk(z0, z1), pk(n0, n1));
    }
    __syncthreads();

    // branch-free column-min store target: lane0 -> real slot, others -> garbage
    u64* sbase = (lane == 0) ? &scolp[w * SP] : &sdump[w * DUMP + lane];

    float m0 = INFF, m1 = INFF, m2 = INFF, m3 = INFF;
    #pragma unroll 8
    for (int jp = 0; jp < SP; jp++) {
        ulonglong2 p0 = scd[2 * jp];      // {cx,cx'},{cy,cy'}
        ulonglong2 p1 = scd[2 * jp + 1];  // {cz,cz'},{cn,cn'}
        // full distances: d = qn + cn - 2 q.c  (qn folded for column comparability)
        u64 t0 = fma2(qx2[0], p0.x, fma2(qy2[0], p0.y, fma2(qz2[0], p1.x, add2(p1.y, qn2[0]))));
        u64 t1 = fma2(qx2[1], p0.x, fma2(qy2[1], p0.y, fma2(qz2[1], p1.x, add2(p1.y, qn2[1]))));
        u64 t2 = fma2(qx2[2], p0.x, fma2(qy2[2], p0.y, fma2(qz2[2], p1.x, add2(p1.y, qn2[2]))));
        u64 t3 = fma2(qx2[3], p0.x, fma2(qy2[3], p0.y, fma2(qz2[3], p1.x, add2(p1.y, qn2[3]))));
        float l0, h0, l1, h1, l2, h2, l3, h3;
        upk(t0, l0, h0); upk(t1, l1, h1); upk(t2, l2, h2); upk(t3, l3, h3);
        // row mins (per query, registers)
        m0 = fminf(m0, fminf(l0, h0));
        m1 = fminf(m1, fminf(l1, h1));
        m2 = fminf(m2, fminf(l2, h2));
        m3 = fminf(m3, fminf(l3, h3));
        // col mins: pre-reduce 4 queries, then one REDUX per candidate
        float cA = fminf(fminf(l0, l1), fminf(l2, l3));
        float cB = fminf(fminf(h0, h1), fminf(h2, h3));
        unsigned ra = __reduce_min_sync(0xffffffffu, __float_as_uint(cA));
        unsigned rb = __reduce_min_sync(0xffffffffu, __float_as_uint(cB));
        // unconditional STS (no BSSY/BSYNC): lane0 writes real slot, rest hit sink
        sbase[jp] = ((u64)rb << 32) | (u64)ra;
    }

    // row mins -> global encoded
    {
        int* gm = g_rmin + b * Nn + qblk * QPB;
        atomicMax(gm + t,           ENC - __float_as_int(m0));
        atomicMax(gm + t + TPB,     ENC - __float_as_int(m1));
        atomicMax(gm + t + 2 * TPB, ENC - __float_as_int(m2));
        atomicMax(gm + t + 3 * TPB, ENC - __float_as_int(m3));
    }
    __syncthreads();

    // col mins: combine 4 warps, -> global encoded (thread t owns pair jp=t)
    {
        u64 v0 = scolp[t], v1 = scolp[SP + t], v2 = scolp[2 * SP + t], v3 = scolp[3 * SP + t];
        unsigned a = min(min((unsigned)v0, (unsigned)v1), min((unsigned)v2, (unsigned)v3));
        unsigned bq = min(min((unsigned)(v0 >> 32), (unsigned)(v1 >> 32)),
                          min((unsigned)(v2 >> 32), (unsigned)(v3 >> 32)));
        int* gc = g_cmin + b * Nn + cs * SC + 2 * t;
        atomicMax(gc,     ENC - (int)a);
        atomicMax(gc + 1, ENC - (int)bq);
    }

    // seg NLL: 32 points per block (warp 0)
    if (t < 32) {
        int idx = bl * 32 + t;
        int lb = s_is64 ? (int)((const long long*)lab)[idx] : ((const int*)lab)[idx];
        float v = prob[idx * NC + lb];
        #pragma unroll
        for (int off = 16; off > 0; off >>= 1)
            v += __shfl_xor_sync(0xffffffffu, v, off);
        if (t == 0) g_fpart[bl] = v;
    }

    // publish: one gpu fence per block (t0), then group tickets
    __syncthreads();
    if (t == 0) {
        __threadfence();
        if (atomicAdd(&g_rowtk[rowg], 1u) == (unsigned)(CSN - 1)) s_rowfin = 1;
        if (atomicAdd(&g_coltk[colg], 1u) == 7u)                  s_colfin = 1;
    }
    __syncthreads();

    if (s_rowfin) {   // row leader: sum 512 query mins; reset
        int4* base = (int4*)(g_rmin + b * Nn + qblk * QPB);
        int4 v = __ldcg(base + t);
        sred[t] = (__int_as_float(ENC - v.x) + __int_as_float(ENC - v.y)) +
                  (__int_as_float(ENC - v.z) + __int_as_float(ENC - v.w));
        __stcg(base + t, make_int4(0, 0, 0, 0));
        __syncthreads();
        #pragma unroll
        for (int s = 64; s > 0; s >>= 1) {
            if (t < s) sred[t] += sred[t + s];
            __syncthreads();
        }
        if (t == 0) {
            g_rowpart[rowg] = sred[0];
            g_rowtk[rowg] = 0u;
            __threadfence();
            if (atomicAdd(&g_ticket, 1u) == (unsigned)(NRG + NCG - 1)) s_last = 1;
        }
        __syncthreads();
    }
    if (s_colfin) {   // col leader: sum 256 candidate mins; reset
        int2* base = (int2*)(g_cmin + b * Nn + cs * SC);
        int2 v = __ldcg(base + t);
        sred[t] = __int_as_float(ENC - v.x) + __int_as_float(ENC - v.y);
        __stcg(base + t, make_int2(0, 0));
        __syncthreads();
        #pragma unroll
        for (int s = 64; s > 0; s >>= 1) {
            if (t < s) sred[t] += sred[t + s];
            __syncthreads();
        }
        if (t == 0) {
            g_colpart[colg] = sred[0];
            g_coltk[colg] = 0u;
            __threadfence();
            if (atomicAdd(&g_ticket, 1u) == (unsigned)(NRG + NCG - 1)) s_last = 1;
        }
        __syncthreads();
    }

    __syncthreads();
    if (s_last) {     // final deterministic combine (one block, L2 reads)
        float v = __ldcg(&g_colpart[t]);              // 128 col-group sums
        if (t < NRG) v += __ldcg(&g_rowpart[t]);      // 64 row-group sums
        float sp = 0.f;
        #pragma unroll
        for (int k = 0; k < NBLK / TPB; k++)
            sp += __ldcg(&g_fpart[t + k * TPB]);      // 1024 seg partials
        sred[t] = v - sp;
        __syncthreads();
        #pragma unroll
        for (int s = 64; s > 0; s >>= 1) {
            if (t < s) sred[t] += sred[t + s];
            __syncthreads();
        }
        if (t == 0) {
            out[0] = sred[0] * (1.0f / (float)BN);
            g_ticket = 0u;   // reset for next graph replay
        }
    }
}

extern "C" void kernel_launch(void* const* d_in, const int* in_sizes, int n_in,
                              void* d_out, int out_size) {
    const float* seg_prob  = (const float*)d_in[0];
    const void*  seg_label = (const void*)d_in[1];
    const float* point_rec = (const float*)d_in[2];
    const float* point     = (const float*)d_in[3];

    fused_kernel<<<dim3(CSN, 8, Bb), TPB>>>(point_rec, point, seg_prob, seg_label,
                                            (float*)d_out);
}